// round 4
// baseline (speedup 1.0000x reference)
#include <cuda_runtime.h>
#include <cstdint>

#define BSZ 32
#define NPT 1024
#define NN (BSZ*NPT)      /* 32768 */
#define TOT (2*NN)        /* 65536 */

#define THRESH 0.1f
#define ENT_WT 1e-4

// ------------------------- scratch (device globals; no mallocs) -------------
__device__ float  g_Sr[TOT];
__device__ float  g_Tr[TOT];
__device__ float4 g_U4[TOT];
__device__ float  g_Sc[TOT];
__device__ float  g_C[TOT];
__device__ float  g_ssq1[BSZ], g_ssq2[BSZ], g_dot[BSZ];
__device__ float  g_T12[BSZ*12], g_T21[BSZ*12];
__device__ float4 g_pin[TOT];   // mat0: p1in2, mat1: p2in1  (w = |p|^2)
__device__ float4 g_pto[TOT];   // mat0: p1to2, mat1: p2to1  (w = |p|^2)
__device__ double g_acc[6];     // 0 cham, 1 corr, 2 ent2, 3 entG, 4 colterm

// ------------------------- helpers ------------------------------------------
__device__ __forceinline__ float wsum(float v) {
#pragma unroll
    for (int o = 16; o; o >>= 1) v += __shfl_down_sync(0xffffffffu, v, o);
    return v;
}

__device__ __forceinline__ float block_sum(float v, float* sm) {
    int lane = threadIdx.x & 31, w = threadIdx.x >> 5;
    v = wsum(v);
    if (lane == 0) sm[w] = v;
    __syncthreads();
    int nw = (blockDim.x + 31) >> 5;
    v = (threadIdx.x < nw) ? sm[threadIdx.x] : 0.f;
    if (w == 0) v = wsum(v);
    return v;
}

// packed f32x2 helpers (FFMA2 — only reachable via PTX)
__device__ __forceinline__ unsigned long long pk2(float a, float b) {
    unsigned long long r;
    asm("mov.b64 %0, {%1,%2};" : "=l"(r) : "f"(a), "f"(b));
    return r;
}
__device__ __forceinline__ void upk2(unsigned long long v, float& a, float& b) {
    asm("mov.b64 {%0,%1}, %2;" : "=f"(a), "=f"(b) : "l"(v));
}
__device__ __forceinline__ unsigned long long mul2(unsigned long long a, unsigned long long b) {
    unsigned long long d;
    asm("mul.rn.f32x2 %0, %1, %2;" : "=l"(d) : "l"(a), "l"(b));
    return d;
}
__device__ __forceinline__ unsigned long long fma2(unsigned long long a, unsigned long long b,
                                                   unsigned long long c) {
    unsigned long long d;
    asm("fma.rn.f32x2 %0, %1, %2, %3;" : "=l"(d) : "l"(a), "l"(b), "l"(c));
    return d;
}

// ------------------------- init + pose ---------------------------------------
__global__ void k_init(const float* __restrict__ scale,
                       const float* __restrict__ rot,
                       const float* __restrict__ trans) {
    int i = blockIdx.x * 256 + threadIdx.x;
    if (i < TOT) { g_Sc[i] = 0.f; g_C[i] = 0.f; }
    if (i < BSZ) { g_ssq1[i] = 0.f; g_ssq2[i] = 0.f; g_dot[i] = 0.f; }
    if (i < 6)   g_acc[i] = 0.0;

    if (blockIdx.x == 0 && threadIdx.x < BSZ) {
        int b = threadIdx.x;
        float s = scale[b];
        float m[9];
#pragma unroll
        for (int k = 0; k < 9; k++) m[k] = s * rot[b*9 + k];
        float t0 = trans[b*3+0], t1 = trans[b*3+1], t2 = trans[b*3+2];

        float* T = g_T12 + b*12;
        T[0]=m[0]; T[1]=m[1]; T[2]=m[2];  T[3]=t0;
        T[4]=m[3]; T[5]=m[4]; T[6]=m[5];  T[7]=t1;
        T[8]=m[6]; T[9]=m[7]; T[10]=m[8]; T[11]=t2;

        float c00=(m[4]*m[8]-m[5]*m[7]), c01=(m[2]*m[7]-m[1]*m[8]), c02=(m[1]*m[5]-m[2]*m[4]);
        float c10=(m[5]*m[6]-m[3]*m[8]), c11=(m[0]*m[8]-m[2]*m[6]), c12=(m[2]*m[3]-m[0]*m[5]);
        float c20=(m[3]*m[7]-m[4]*m[6]), c21=(m[1]*m[6]-m[0]*m[7]), c22=(m[0]*m[4]-m[1]*m[3]);
        float det = m[0]*c00 + m[1]*c10 + m[2]*c20;
        float id = 1.f/det;
        float i00=c00*id,i01=c01*id,i02=c02*id;
        float i10=c10*id,i11=c11*id,i12=c12*id;
        float i20=c20*id,i21=c21*id,i22=c22*id;
        float u0 = -(i00*t0 + i01*t1 + i02*t2);
        float u1 = -(i10*t0 + i11*t1 + i12*t2);
        float u2 = -(i20*t0 + i21*t1 + i22*t2);
        float* V = g_T21 + b*12;
        V[0]=i00; V[1]=i01; V[2]=i02;  V[3]=u0;
        V[4]=i10; V[5]=i11; V[6]=i12;  V[7]=u1;
        V[8]=i20; V[9]=i21; V[10]=i22; V[11]=u2;
    }
}

// ------------------------- fused single pass over both matrices --------------
// grid (32 batches, 32 row-blocks). 256 threads = 8 warps = 2 row-groups of
// 128 threads; each group owns one full row per iteration (16 iterations,
// 32 rows/block). Per thread: 8 columns (2 float4 chunks) of each matrix.
// Computes: row sums Sr/Tr/U (exp-weighted), column sums Sc and
// C = sum_n exp(A[n,m])*invSr[n] (via register-stashed exps), ssq, dot.
__global__ __launch_bounds__(256)
void k_fused(const float* __restrict__ A1, const float* __restrict__ A2,
             const float* __restrict__ P1, const float* __restrict__ P2) {
    __shared__ float p1x[NPT], p1y[NPT], p1z[NPT];
    __shared__ float p2x[NPT], p2y[NPT], p2z[NPT];
    __shared__ float red[8*10];
    __shared__ float bc[2][2];
    __shared__ float fl[4096];   // merge buffer: [Sc1|C1|Sc2|C2] x 1024
    __shared__ float rsm[32];

    const int b  = blockIdx.x;
    const int rb = blockIdx.y;
    const int tid = threadIdx.x;
    const int warp = tid >> 5, lane = tid & 31;
    const int group = warp >> 2;         // 0 or 1
    const int gtid  = tid & 127;

    const float* P1g = P1 + (size_t)b*NPT*3;
    const float* P2g = P2 + (size_t)b*NPT*3;
    for (int i = tid; i < NPT; i += 256) {
        p1x[i]=P1g[i*3+0]; p1y[i]=P1g[i*3+1]; p1z[i]=P1g[i*3+2];
        p2x[i]=P2g[i*3+0]; p2y[i]=P2g[i*3+1]; p2z[i]=P2g[i*3+2];
    }
    __syncthreads();

    const float* A1b = A1 + ((size_t)b << 20);
    const float* A2b = A2 + ((size_t)b << 20);

    float colSc1[8], colC1[8], colSc2[8], colC2[8];
#pragma unroll
    for (int j = 0; j < 8; j++) { colSc1[j]=0.f; colC1[j]=0.f; colSc2[j]=0.f; colC2[j]=0.f; }
    float ss1 = 0.f, ss2 = 0.f, dp = 0.f;

    const int c0 = gtid*4;          // chunk-0 column
    const int c1 = 512 + gtid*4;    // chunk-1 column

    for (int it = 0; it < 16; it++) {
        const int row = rb*32 + it*2 + group;
        const float* A1r = A1b + (size_t)row*NPT;
        const float* A2r = A2b + (size_t)row*NPT;

        float eS1[8], eS2[8];
        float s1=0.f, t1=0.f, u1x=0.f, u1y=0.f, u1z=0.f;
        float s2=0.f, t2=0.f, u2x=0.f, u2y=0.f, u2z=0.f;

#pragma unroll
        for (int c = 0; c < 2; c++) {
            const int col = c ? c1 : c0;
            const float4 a1 = __ldcs((const float4*)&A1r[col]);
            const float4 a2 = __ldcs((const float4*)&A2r[col]);
            const float4 q2xv = *(const float4*)&p2x[col];
            const float4 q2yv = *(const float4*)&p2y[col];
            const float4 q2zv = *(const float4*)&p2z[col];
            const float4 q1xv = *(const float4*)&p1x[col];
            const float4 q1yv = *(const float4*)&p1y[col];
            const float4 q1zv = *(const float4*)&p1z[col];
#define PROC(j, cmp) { \
    float a1v=a1.cmp, a2v=a2.cmp; \
    float e1=__expf(a1v), e2=__expf(a2v); \
    eS1[c*4+j]=e1; eS2[c*4+j]=e2; \
    s1+=e1; t1=fmaf(e1,a1v,t1); \
    u1x=fmaf(e1,q2xv.cmp,u1x); u1y=fmaf(e1,q2yv.cmp,u1y); u1z=fmaf(e1,q2zv.cmp,u1z); \
    s2+=e2; t2=fmaf(e2,a2v,t2); \
    u2x=fmaf(e2,q1xv.cmp,u2x); u2y=fmaf(e2,q1yv.cmp,u2y); u2z=fmaf(e2,q1zv.cmp,u2z); \
    colSc1[c*4+j]+=e1; colSc2[c*4+j]+=e2; \
    ss1=fmaf(a1v,a1v,ss1); ss2=fmaf(a2v,a2v,ss2); dp=fmaf(a1v,a2v,dp); }
            PROC(0,x) PROC(1,y) PROC(2,z) PROC(3,w)
#undef PROC
        }

        // reduce 10 row values across the 128 threads of this group
        float v0=wsum(s1),  v1=wsum(t1),  v2=wsum(u1x), v3=wsum(u1y), v4=wsum(u1z);
        float v5=wsum(s2),  v6=wsum(t2),  v7=wsum(u2x), v8=wsum(u2y), v9=wsum(u2z);
        if (lane == 0) {
            float* r = red + warp*10;
            r[0]=v0; r[1]=v1; r[2]=v2; r[3]=v3; r[4]=v4;
            r[5]=v5; r[6]=v6; r[7]=v7; r[8]=v8; r[9]=v9;
        }
        __syncthreads();
        if (gtid == 0) {
            const float* r0 = red + group*40;
            float r[10];
#pragma unroll
            for (int k = 0; k < 10; k++)
                r[k] = r0[k] + r0[10+k] + r0[20+k] + r0[30+k];
            size_t i1 = (size_t)b*NPT + row;
            float inv1 = 1.f/r[0], inv2 = 1.f/r[5];
            g_Sr[i1]    = r[0]; g_Tr[i1]    = r[1];
            g_U4[i1]    = make_float4(r[2], r[3], r[4], 0.f);
            g_Sr[i1+NN] = r[5]; g_Tr[i1+NN] = r[6];
            g_U4[i1+NN] = make_float4(r[7], r[8], r[9], 0.f);
            bc[group][0] = inv1; bc[group][1] = inv2;
        }
        __syncthreads();
        const float inv1 = bc[group][0];
        const float inv2 = bc[group][1];
#pragma unroll
        for (int j = 0; j < 8; j++) {
            colC1[j] = fmaf(eS1[j], inv1, colC1[j]);
            colC2[j] = fmaf(eS2[j], inv2, colC2[j]);
        }
    }

    // ---- block sums for ssq / dot
    float v = block_sum(ss1, rsm);
    if (tid == 0) atomicAdd(&g_ssq1[b], v);
    __syncthreads();
    v = block_sum(ss2, rsm);
    if (tid == 0) atomicAdd(&g_ssq2[b], v);
    __syncthreads();
    v = block_sum(dp, rsm);
    if (tid == 0) atomicAdd(&g_dot[b], v);
    __syncthreads();

    // ---- merge the two row-groups' column accumulators via smem, then flush
    if (group == 0) {
#pragma unroll
        for (int c = 0; c < 2; c++) {
#pragma unroll
            for (int j = 0; j < 4; j++) {
                int col = (c ? c1 : c0) + j;
                fl[col]        = colSc1[c*4+j];
                fl[1024 + col] = colC1[c*4+j];
                fl[2048 + col] = colSc2[c*4+j];
                fl[3072 + col] = colC2[c*4+j];
            }
        }
    }
    __syncthreads();
    if (group == 1) {
#pragma unroll
        for (int c = 0; c < 2; c++) {
#pragma unroll
            for (int j = 0; j < 4; j++) {
                int col = (c ? c1 : c0) + j;
                fl[col]        += colSc1[c*4+j];
                fl[1024 + col] += colC1[c*4+j];
                fl[2048 + col] += colSc2[c*4+j];
                fl[3072 + col] += colC2[c*4+j];
            }
        }
    }
    __syncthreads();

    const int arr = tid >> 6;           // 0..3, fixed per thread
    const size_t o = (size_t)b*NPT;
    float* dst = (arr==0) ? (g_Sc + o) : (arr==1) ? (g_C + o)
               : (arr==2) ? (g_Sc + NN + o) : (g_C + NN + o);
#pragma unroll
    for (int k = 0; k < 16; k++) {
        int idx = tid*16 + k;
        atomicAdd(&dst[idx & 1023], fl[idx]);
    }
}

// ------------------------- row finalize --------------------------------------
__global__ __launch_bounds__(256)
void k_rowfinal(const float* __restrict__ P1, const float* __restrict__ P2) {
    __shared__ float rsm[32];
    int idx = blockIdx.x * 256 + threadIdx.x;   // < 65536
    int mat = idx >> 15;
    int b   = (idx >> 10) & 31;
    int n   = idx & 1023;

    float sr  = g_Sr[idx];
    float isr = 1.f / sr;
    float gq  = g_Tr[idx] * isr;                 // sum_m sa*A for this row
    float e2p = __logf(sr) - gq;

    float4 u = g_U4[idx];
    float px = u.x*isr, py = u.y*isr, pz = u.z*isr;
    g_pin[idx] = make_float4(px, py, pz, px*px+py*py+pz*pz);

    const float* pts = mat ? P2 : P1;
    const float* T   = (mat ? g_T21 : g_T12) + b*12;
    float x0 = pts[((size_t)b*NPT+n)*3+0];
    float x1 = pts[((size_t)b*NPT+n)*3+1];
    float x2 = pts[((size_t)b*NPT+n)*3+2];
    float y0 = T[0]*x0 + T[1]*x1 + T[2]*x2 + T[3];
    float y1 = T[4]*x0 + T[5]*x1 + T[6]*x2 + T[7];
    float y2 = T[8]*x0 + T[9]*x1 + T[10]*x2 + T[11];
    g_pto[idx] = make_float4(y0, y1, y2, y0*y0+y1*y1+y2*y2);

#define HUBER(d) ((d) > THRESH ? (d) - 0.5f*THRESH : (d)*(d)*(0.5f/THRESH))
    float d0 = fabsf(px-y0), d1 = fabsf(py-y1), d2 = fabsf(pz-y2);
    float corr = HUBER(d0) + HUBER(d1) + HUBER(d2);
#undef HUBER

    float v = block_sum(e2p, rsm);
    if (threadIdx.x == 0) atomicAdd(&g_acc[2], (double)v);
    __syncthreads();
    v = block_sum(gq, rsm);
    if (threadIdx.x == 0) atomicAdd(&g_acc[3], (double)v);
    __syncthreads();
    v = block_sum(corr, rsm);
    if (threadIdx.x == 0) atomicAdd(&g_acc[1], (double)v);
}

// ------------------------- column finalize -----------------------------------
__global__ __launch_bounds__(256)
void k_colfinal() {
    __shared__ float rsm[32];
    int i = blockIdx.x * 256 + threadIdx.x;   // < 65536
    float v = __logf(g_Sc[i]) * g_C[i];
    v = block_sum(v, rsm);
    if (threadIdx.x == 0) atomicAdd(&g_acc[4], (double)v);
}

// ------------------------- chamfer (packed f32x2) ----------------------------
// grid 128: bx -> b(32) x dir(2) x prob(2). 512 threads, 2 x-points each.
__global__ __launch_bounds__(512)
void k_chamfer() {
    __shared__ ulonglong2 sYA[NPT/2];   // (x-pair, y-pair)
    __shared__ ulonglong2 sYB[NPT/2];   // (z-pair, w-pair)
    __shared__ float rsm[32];
    int bx = blockIdx.x;
    int b = bx & 31; int dir = (bx >> 5) & 1; int prob = bx >> 6;
    size_t base = (size_t)(prob*BSZ + b) * NPT;
    const float4* X = dir ? (g_pin + base) : (g_pto + base);
    const float4* Y = dir ? (g_pto + base) : (g_pin + base);
    int tid = threadIdx.x;

    {
        float4 y0 = Y[2*tid], y1 = Y[2*tid+1];
        sYA[tid] = make_ulonglong2(pk2(y0.x, y1.x), pk2(y0.y, y1.y));
        sYB[tid] = make_ulonglong2(pk2(y0.z, y1.z), pk2(y0.w, y1.w));
    }
    __syncthreads();

    float4 xa = X[tid];
    float4 xb = X[tid + 512];
    unsigned long long ax = pk2(xa.x, xa.x), ay = pk2(xa.y, xa.y), az = pk2(xa.z, xa.z);
    unsigned long long bx2 = pk2(xb.x, xb.x), by = pk2(xb.y, xb.y), bz = pk2(xb.z, xb.z);
    const unsigned long long neg2 = pk2(-2.f, -2.f);

    float mna = 1e30f, mnb = 1e30f;
#pragma unroll 4
    for (int m = 0; m < NPT/2; m++) {
        ulonglong2 A = sYA[m];
        ulonglong2 B = sYB[m];
        unsigned long long d, v;
        float lo, hi;
        d = mul2(ax, A.x); d = fma2(ay, A.y, d); d = fma2(az, B.x, d);
        v = fma2(neg2, d, B.y);
        upk2(v, lo, hi);
        mna = fminf(mna, fminf(lo, hi));
        d = mul2(bx2, A.x); d = fma2(by, A.y, d); d = fma2(bz, B.x, d);
        v = fma2(neg2, d, B.y);
        upk2(v, lo, hi);
        mnb = fminf(mnb, fminf(lo, hi));
    }
    float dsum = fmaxf(xa.w + mna, 0.f) + fmaxf(xb.w + mnb, 0.f);
    float v = block_sum(dsum, rsm);
    if (tid == 0) atomicAdd(&g_acc[0], (double)v);
}

// ------------------------- final combine -------------------------------------
__global__ void k_final(float* __restrict__ out) {
    int b = threadIdx.x;   // 32 threads
    float n1 = sqrtf(g_ssq1[b]);
    float n2 = sqrtf(g_ssq2[b]);
    float cosv = 1.f - g_dot[b] / (fmaxf(n1, 1e-8f) * fmaxf(n2, 1e-8f));
    cosv = wsum(cosv);
    if (b == 0) {
        double invBN = 1.0 / (double)(BSZ * NPT);
        double total = g_acc[0] * invBN
                     + g_acc[1] * invBN
                     + ENT_WT * invBN * (g_acc[2] + g_acc[4] - g_acc[3])
                     + (double)cosv / (double)BSZ;
        out[0] = (float)total;
    }
}

// ------------------------- launch --------------------------------------------
extern "C" void kernel_launch(void* const* d_in, const int* in_sizes, int n_in,
                              void* d_out, int out_size) {
    const float* P1 = (const float*)d_in[0];
    const float* P2 = (const float*)d_in[1];
    const float* A1 = (const float*)d_in[2];
    const float* A2 = (const float*)d_in[3];
    const float* sc = (const float*)d_in[4];
    const float* rt = (const float*)d_in[5];
    const float* tr = (const float*)d_in[6];
    float* out = (float*)d_out;

    k_init<<<TOT/256, 256>>>(sc, rt, tr);
    k_fused<<<dim3(BSZ, 32), 256>>>(A1, A2, P1, P2);
    k_rowfinal<<<TOT/256, 256>>>(P1, P2);
    k_colfinal<<<TOT/256, 256>>>();
    k_chamfer<<<128, 512>>>();
    k_final<<<1, 32>>>(out);
}

// round 6
// speedup vs baseline: 1.0820x; 1.0820x over previous
#include <cuda_runtime.h>
#include <cuda_fp16.h>
#include <cstdint>

#define BSZ 32
#define NPT 1024
#define NN (BSZ*NPT)      /* 32768 */
#define TOT (2*NN)        /* 65536 */

#define THRESH 0.1f
#define ENT_WT 1e-4

// ------------------------- scratch (device globals; no mallocs) -------------
__device__ uint32_t g_E[2u*BSZ*NPT*256];   // 64 MiB: exp(A) as e4m3, 4 per u32
__device__ float  g_invSr[TOT];
__device__ float  g_Sc[TOT];
__device__ float  g_C[TOT];
__device__ float  g_ssq1[BSZ], g_ssq2[BSZ], g_dot[BSZ];
__device__ float  g_T12[BSZ*12], g_T21[BSZ*12];
__device__ float4 g_pin[TOT];   // mat0: p1in2, mat1: p2in1  (w = |p|^2)
__device__ float4 g_pto[TOT];   // mat0: p1to2, mat1: p2to1  (w = |p|^2)
__device__ double g_acc[6];     // 0 cham, 1 corr, 2 ent2, 3 entG, 4 colterm

// ------------------------- helpers ------------------------------------------
__device__ __forceinline__ float wsum(float v) {
#pragma unroll
    for (int o = 16; o; o >>= 1) v += __shfl_down_sync(0xffffffffu, v, o);
    return v;
}

__device__ __forceinline__ float block_sum(float v, float* sm) {
    int lane = threadIdx.x & 31, w = threadIdx.x >> 5;
    v = wsum(v);
    if (lane == 0) sm[w] = v;
    __syncthreads();
    int nw = (blockDim.x + 31) >> 5;
    v = (threadIdx.x < nw) ? sm[threadIdx.x] : 0.f;
    if (w == 0) v = wsum(v);
    return v;
}

// packed f32x2 helpers (FFMA2 — only reachable via PTX)
__device__ __forceinline__ unsigned long long pk2(float a, float b) {
    unsigned long long r;
    asm("mov.b64 %0, {%1,%2};" : "=l"(r) : "f"(a), "f"(b));
    return r;
}
__device__ __forceinline__ void upk2(unsigned long long v, float& a, float& b) {
    asm("mov.b64 {%0,%1}, %2;" : "=f"(a), "=f"(b) : "l"(v));
}
__device__ __forceinline__ unsigned long long mul2(unsigned long long a, unsigned long long b) {
    unsigned long long d;
    asm("mul.rn.f32x2 %0, %1, %2;" : "=l"(d) : "l"(a), "l"(b));
    return d;
}
__device__ __forceinline__ unsigned long long fma2(unsigned long long a, unsigned long long b,
                                                   unsigned long long c) {
    unsigned long long d;
    asm("fma.rn.f32x2 %0, %1, %2, %3;" : "=l"(d) : "l"(a), "l"(b), "l"(c));
    return d;
}

// fp8 e4m3 pack/unpack
__device__ __forceinline__ uint32_t pack_e4m3x4(float f0, float f1, float f2, float f3) {
    uint32_t r;
    asm("{\n\t.reg .b16 lo, hi;\n\t"
        "cvt.rn.satfinite.e4m3x2.f32 lo, %2, %1;\n\t"
        "cvt.rn.satfinite.e4m3x2.f32 hi, %4, %3;\n\t"
        "mov.b32 %0, {lo, hi};\n\t}"
        : "=r"(r) : "f"(f0), "f"(f1), "f"(f2), "f"(f3));
    return r;
}
__device__ __forceinline__ void unpack_e4m3x4(uint32_t v, uint32_t& h01, uint32_t& h23) {
    asm("{\n\t.reg .b16 lo, hi;\n\t"
        "mov.b32 {lo, hi}, %2;\n\t"
        "cvt.rn.f16x2.e4m3x2 %0, lo;\n\t"
        "cvt.rn.f16x2.e4m3x2 %1, hi;\n\t}"
        : "=r"(h01), "=r"(h23) : "r"(v));
}
__device__ __forceinline__ uint32_t hadd2u(uint32_t a, uint32_t b) {
    uint32_t d; asm("add.rn.f16x2 %0, %1, %2;" : "=r"(d) : "r"(a), "r"(b)); return d;
}
__device__ __forceinline__ uint32_t hfma2u(uint32_t a, uint32_t b, uint32_t c) {
    uint32_t d; asm("fma.rn.f16x2 %0, %1, %2, %3;" : "=r"(d) : "r"(a), "r"(b), "r"(c)); return d;
}
__device__ __forceinline__ uint32_t bcast_h2(float w) {
    uint32_t d;
    asm("{\n\t.reg .b16 h;\n\tcvt.rn.f16.f32 h, %1;\n\tmov.b32 %0, {h, h};\n\t}"
        : "=r"(d) : "f"(w));
    return d;
}
__device__ __forceinline__ void h2_to_f2(uint32_t v, float& a, float& b) {
    asm("{\n\t.reg .b16 lo, hi;\n\tmov.b32 {lo, hi}, %2;\n\t"
        "cvt.f32.f16 %0, lo;\n\tcvt.f32.f16 %1, hi;\n\t}"
        : "=f"(a), "=f"(b) : "r"(v));
}

// ------------------------- init + pose ---------------------------------------
__global__ void k_init(const float* __restrict__ scale,
                       const float* __restrict__ rot,
                       const float* __restrict__ trans) {
    int i = blockIdx.x * 256 + threadIdx.x;
    if (i < TOT) { g_Sc[i] = 0.f; g_C[i] = 0.f; }
    if (i < BSZ) { g_ssq1[i] = 0.f; g_ssq2[i] = 0.f; g_dot[i] = 0.f; }
    if (i < 6)   g_acc[i] = 0.0;

    if (blockIdx.x == 0 && threadIdx.x < BSZ) {
        int b = threadIdx.x;
        float s = scale[b];
        float m[9];
#pragma unroll
        for (int k = 0; k < 9; k++) m[k] = s * rot[b*9 + k];
        float t0 = trans[b*3+0], t1 = trans[b*3+1], t2 = trans[b*3+2];

        float* T = g_T12 + b*12;
        T[0]=m[0]; T[1]=m[1]; T[2]=m[2];  T[3]=t0;
        T[4]=m[3]; T[5]=m[4]; T[6]=m[5];  T[7]=t1;
        T[8]=m[6]; T[9]=m[7]; T[10]=m[8]; T[11]=t2;

        float c00=(m[4]*m[8]-m[5]*m[7]), c01=(m[2]*m[7]-m[1]*m[8]), c02=(m[1]*m[5]-m[2]*m[4]);
        float c10=(m[5]*m[6]-m[3]*m[8]), c11=(m[0]*m[8]-m[2]*m[6]), c12=(m[2]*m[3]-m[0]*m[5]);
        float c20=(m[3]*m[7]-m[4]*m[6]), c21=(m[1]*m[6]-m[0]*m[7]), c22=(m[0]*m[4]-m[1]*m[3]);
        float det = m[0]*c00 + m[1]*c10 + m[2]*c20;
        float id = 1.f/det;
        float i00=c00*id,i01=c01*id,i02=c02*id;
        float i10=c10*id,i11=c11*id,i12=c12*id;
        float i20=c20*id,i21=c21*id,i22=c22*id;
        float u0 = -(i00*t0 + i01*t1 + i02*t2);
        float u1 = -(i10*t0 + i11*t1 + i12*t2);
        float u2 = -(i20*t0 + i21*t1 + i22*t2);
        float* V = g_T21 + b*12;
        V[0]=i00; V[1]=i01; V[2]=i02;  V[3]=u0;
        V[4]=i10; V[5]=i11; V[6]=i12;  V[7]=u1;
        V[8]=i20; V[9]=i21; V[10]=i22; V[11]=u2;
    }
}

// ------------------------- pass 1 --------------------------------------------
// grid (32, 128), 256 threads = 8 warps, 1 full row per warp (both matrices).
// Streams A, writes exp(A) as e4m3, computes row sums + row finalize inline
// (invSr, pin, pto, Huber corr, entropy-axis2 parts), plus ssq/dot.
__global__ __launch_bounds__(256, 3)
void k_pass1(const float* __restrict__ A1, const float* __restrict__ A2,
             const float* __restrict__ P1, const float* __restrict__ P2) {
    __shared__ float p1x[NPT], p1y[NPT], p1z[NPT];
    __shared__ float p2x[NPT], p2y[NPT], p2z[NPT];
    __shared__ float sT[24];
    __shared__ float rsm[32];

    const int b  = blockIdx.x;
    const int rb = blockIdx.y;
    const int tid = threadIdx.x;
    const int warp = tid >> 5, lane = tid & 31;

    const float* P1g = P1 + (size_t)b*NPT*3;
    const float* P2g = P2 + (size_t)b*NPT*3;
    for (int i = tid; i < NPT; i += 256) {
        p1x[i]=P1g[i*3+0]; p1y[i]=P1g[i*3+1]; p1z[i]=P1g[i*3+2];
        p2x[i]=P2g[i*3+0]; p2y[i]=P2g[i*3+1]; p2z[i]=P2g[i*3+2];
    }
    if (tid < 12)            sT[tid]      = g_T12[b*12 + tid];
    else if (tid < 24)       sT[tid]      = g_T21[b*12 + tid - 12];
    __syncthreads();

    const int row = rb*8 + warp;
    const float* A1r = A1 + ((size_t)b << 20) + ((size_t)row << 10);
    const float* A2r = A2 + ((size_t)b << 20) + ((size_t)row << 10);
    uint32_t* E1r = g_E + ((size_t)b << 18) + row*256;
    uint32_t* E2r = g_E + ((size_t)(BSZ + b) << 18) + row*256;

    float s1=0.f, t1=0.f, u1x=0.f, u1y=0.f, u1z=0.f;
    float s2=0.f, t2=0.f, u2x=0.f, u2y=0.f, u2z=0.f;
    float ss1=0.f, ss2=0.f, dp=0.f;

#pragma unroll
    for (int c = 0; c < 8; c++) {
        const int col = c*128 + lane*4;
        const float4 a1 = __ldcs((const float4*)&A1r[col]);
        const float4 a2 = __ldcs((const float4*)&A2r[col]);
        const float4 q2xv = *(const float4*)&p2x[col];
        const float4 q2yv = *(const float4*)&p2y[col];
        const float4 q2zv = *(const float4*)&p2z[col];
        const float4 q1xv = *(const float4*)&p1x[col];
        const float4 q1yv = *(const float4*)&p1y[col];
        const float4 q1zv = *(const float4*)&p1z[col];
        float e1v[4], e2v[4];
#define PROC(j, cmp) { \
    float a1v=a1.cmp, a2v=a2.cmp; \
    float e1=__expf(a1v), e2=__expf(a2v); \
    e1v[j]=e1; e2v[j]=e2; \
    s1+=e1; t1=fmaf(e1,a1v,t1); \
    u1x=fmaf(e1,q2xv.cmp,u1x); u1y=fmaf(e1,q2yv.cmp,u1y); u1z=fmaf(e1,q2zv.cmp,u1z); \
    s2+=e2; t2=fmaf(e2,a2v,t2); \
    u2x=fmaf(e2,q1xv.cmp,u2x); u2y=fmaf(e2,q1yv.cmp,u2y); u2z=fmaf(e2,q1zv.cmp,u2z); \
    ss1=fmaf(a1v,a1v,ss1); ss2=fmaf(a2v,a2v,ss2); dp=fmaf(a1v,a2v,dp); }
        PROC(0,x) PROC(1,y) PROC(2,z) PROC(3,w)
#undef PROC
        E1r[col >> 2] = pack_e4m3x4(e1v[0], e1v[1], e1v[2], e1v[3]);
        E2r[col >> 2] = pack_e4m3x4(e2v[0], e2v[1], e2v[2], e2v[3]);
    }

    // full-row reductions (warp-local)
    s1=wsum(s1); t1=wsum(t1); u1x=wsum(u1x); u1y=wsum(u1y); u1z=wsum(u1z);
    s2=wsum(s2); t2=wsum(t2); u2x=wsum(u2x); u2y=wsum(u2y); u2z=wsum(u2z);

    float corrA = 0.f, e2pA = 0.f, gqA = 0.f;
    if (lane == 0) {
#define HUBER(d) ((d) > THRESH ? (d) - 0.5f*THRESH : (d)*(d)*(0.5f/THRESH))
        // matrix 1 row
        {
            size_t i1 = (size_t)b*NPT + row;
            float isr = 1.f/s1;
            g_invSr[i1] = isr;
            float gq = t1*isr;
            float e2p = __logf(s1) - gq;
            float px=u1x*isr, py=u1y*isr, pz=u1z*isr;
            g_pin[i1] = make_float4(px, py, pz, px*px+py*py+pz*pz);
            float x0=p1x[row], x1=p1y[row], x2=p1z[row];
            float y0 = sT[0]*x0 + sT[1]*x1 + sT[2]*x2 + sT[3];
            float y1 = sT[4]*x0 + sT[5]*x1 + sT[6]*x2 + sT[7];
            float y2 = sT[8]*x0 + sT[9]*x1 + sT[10]*x2 + sT[11];
            g_pto[i1] = make_float4(y0, y1, y2, y0*y0+y1*y1+y2*y2);
            float d0=fabsf(px-y0), d1=fabsf(py-y1), d2=fabsf(pz-y2);
            corrA += HUBER(d0)+HUBER(d1)+HUBER(d2);
            e2pA += e2p; gqA += gq;
        }
        // matrix 2 row
        {
            size_t i2 = (size_t)NN + (size_t)b*NPT + row;
            float isr = 1.f/s2;
            g_invSr[i2] = isr;
            float gq = t2*isr;
            float e2p = __logf(s2) - gq;
            float px=u2x*isr, py=u2y*isr, pz=u2z*isr;
            g_pin[i2] = make_float4(px, py, pz, px*px+py*py+pz*pz);
            float x0=p2x[row], x1=p2y[row], x2=p2z[row];
            float y0 = sT[12]*x0 + sT[13]*x1 + sT[14]*x2 + sT[15];
            float y1 = sT[16]*x0 + sT[17]*x1 + sT[18]*x2 + sT[19];
            float y2 = sT[20]*x0 + sT[21]*x1 + sT[22]*x2 + sT[23];
            g_pto[i2] = make_float4(y0, y1, y2, y0*y0+y1*y1+y2*y2);
            float d0=fabsf(px-y0), d1=fabsf(py-y1), d2=fabsf(pz-y2);
            corrA += HUBER(d0)+HUBER(d1)+HUBER(d2);
            e2pA += e2p; gqA += gq;
        }
#undef HUBER
    }

    float v = block_sum(ss1, rsm);
    if (tid == 0) atomicAdd(&g_ssq1[b], v);
    __syncthreads();
    v = block_sum(ss2, rsm);
    if (tid == 0) atomicAdd(&g_ssq2[b], v);
    __syncthreads();
    v = block_sum(dp, rsm);
    if (tid == 0) atomicAdd(&g_dot[b], v);
    __syncthreads();
    v = block_sum(corrA, rsm);
    if (tid == 0) atomicAdd(&g_acc[1], (double)v);
    __syncthreads();
    v = block_sum(e2pA, rsm);
    if (tid == 0) atomicAdd(&g_acc[2], (double)v);
    __syncthreads();
    v = block_sum(gqA, rsm);
    if (tid == 0) atomicAdd(&g_acc[3], (double)v);
}

// ------------------------- pass 2: fp8 column pass ----------------------------
// grid 512: bx -> chunk(8, 128 rows) x b(32) x mat(2). 256 threads:
// sub = tid>>6 handles rows chunk*128+sub*32 .. +31; ct = tid&63 handles
// 16 columns (one uint4 of fp8 per row). Accumulate Sc/C in f16x2, flush f32.
__global__ __launch_bounds__(256)
void k_pass2() {
    __shared__ float isr[128];
    const int bx = blockIdx.x;
    const int chunk = bx & 7, b = (bx >> 3) & 31, mat = bx >> 8;
    const int tid = threadIdx.x;
    const int sub = tid >> 6, ct = tid & 63;

    if (tid < 128)
        isr[tid] = g_invSr[(size_t)(mat*BSZ + b)*NPT + chunk*128 + tid];
    __syncthreads();

    const int row0 = chunk*128 + sub*32;
    const uint4* Ep = (const uint4*)(g_E + ((size_t)(mat*BSZ + b) << 18) + row0*256) + ct;

    uint32_t sc[8], cc[8];
#pragma unroll
    for (int k = 0; k < 8; k++) { sc[k] = 0u; cc[k] = 0u; }

#pragma unroll 4
    for (int r = 0; r < 32; r++) {
        uint4 v = Ep[(size_t)r*64];
        uint32_t w2 = bcast_h2(isr[sub*32 + r]);
        uint32_t h0, h1;
        unpack_e4m3x4(v.x, h0, h1);
        sc[0]=hadd2u(sc[0],h0); cc[0]=hfma2u(h0,w2,cc[0]);
        sc[1]=hadd2u(sc[1],h1); cc[1]=hfma2u(h1,w2,cc[1]);
        unpack_e4m3x4(v.y, h0, h1);
        sc[2]=hadd2u(sc[2],h0); cc[2]=hfma2u(h0,w2,cc[2]);
        sc[3]=hadd2u(sc[3],h1); cc[3]=hfma2u(h1,w2,cc[3]);
        unpack_e4m3x4(v.z, h0, h1);
        sc[4]=hadd2u(sc[4],h0); cc[4]=hfma2u(h0,w2,cc[4]);
        sc[5]=hadd2u(sc[5],h1); cc[5]=hfma2u(h1,w2,cc[5]);
        unpack_e4m3x4(v.w, h0, h1);
        sc[6]=hadd2u(sc[6],h0); cc[6]=hfma2u(h0,w2,cc[6]);
        sc[7]=hadd2u(sc[7],h1); cc[7]=hfma2u(h1,w2,cc[7]);
    }

    const size_t o = (size_t)(mat*BSZ + b)*NPT + ct*16;
#pragma unroll
    for (int k = 0; k < 8; k++) {
        float a0, a1;
        h2_to_f2(sc[k], a0, a1);
        atomicAdd(&g_Sc[o + 2*k],     a0);
        atomicAdd(&g_Sc[o + 2*k + 1], a1);
        h2_to_f2(cc[k], a0, a1);
        atomicAdd(&g_C[o + 2*k],      a0);
        atomicAdd(&g_C[o + 2*k + 1],  a1);
    }
}

// ------------------------- column finalize -----------------------------------
__global__ __launch_bounds__(256)
void k_colfinal() {
    __shared__ float rsm[32];
    int i = blockIdx.x * 256 + threadIdx.x;   // < 65536
    float v = __logf(g_Sc[i]) * g_C[i];
    v = block_sum(v, rsm);
    if (threadIdx.x == 0) atomicAdd(&g_acc[4], (double)v);
}

// ------------------------- chamfer (packed f32x2) ----------------------------
// grid 128: bx -> b(32) x dir(2) x prob(2). 512 threads, 2 x-points each.
__global__ __launch_bounds__(512)
void k_chamfer() {
    __shared__ ulonglong2 sYA[NPT/2];   // (x-pair, y-pair)
    __shared__ ulonglong2 sYB[NPT/2];   // (z-pair, w-pair)
    __shared__ float rsm[32];
    int bx = blockIdx.x;
    int b = bx & 31; int dir = (bx >> 5) & 1; int prob = bx >> 6;
    size_t base = (size_t)(prob*BSZ + b) * NPT;
    const float4* X = dir ? (g_pin + base) : (g_pto + base);
    const float4* Y = dir ? (g_pto + base) : (g_pin + base);
    int tid = threadIdx.x;

    {
        float4 y0 = Y[2*tid], y1 = Y[2*tid+1];
        sYA[tid] = make_ulonglong2(pk2(y0.x, y1.x), pk2(y0.y, y1.y));
        sYB[tid] = make_ulonglong2(pk2(y0.z, y1.z), pk2(y0.w, y1.w));
    }
    __syncthreads();

    float4 xa = X[tid];
    float4 xb = X[tid + 512];
    unsigned long long ax = pk2(xa.x, xa.x), ay = pk2(xa.y, xa.y), az = pk2(xa.z, xa.z);
    unsigned long long bx2 = pk2(xb.x, xb.x), by = pk2(xb.y, xb.y), bz = pk2(xb.z, xb.z);
    const unsigned long long neg2 = pk2(-2.f, -2.f);

    float mna = 1e30f, mnb = 1e30f;
#pragma unroll 4
    for (int m = 0; m < NPT/2; m++) {
        ulonglong2 A = sYA[m];
        ulonglong2 B = sYB[m];
        unsigned long long d, v;
        float lo, hi;
        d = mul2(ax, A.x); d = fma2(ay, A.y, d); d = fma2(az, B.x, d);
        v = fma2(neg2, d, B.y);
        upk2(v, lo, hi);
        mna = fminf(mna, fminf(lo, hi));
        d = mul2(bx2, A.x); d = fma2(by, A.y, d); d = fma2(bz, B.x, d);
        v = fma2(neg2, d, B.y);
        upk2(v, lo, hi);
        mnb = fminf(mnb, fminf(lo, hi));
    }
    float dsum = fmaxf(xa.w + mna, 0.f) + fmaxf(xb.w + mnb, 0.f);
    float v = block_sum(dsum, rsm);
    if (tid == 0) atomicAdd(&g_acc[0], (double)v);
}

// ------------------------- final combine -------------------------------------
__global__ void k_final(float* __restrict__ out) {
    int b = threadIdx.x;   // 32 threads
    float n1 = sqrtf(g_ssq1[b]);
    float n2 = sqrtf(g_ssq2[b]);
    float cosv = 1.f - g_dot[b] / (fmaxf(n1, 1e-8f) * fmaxf(n2, 1e-8f));
    cosv = wsum(cosv);
    if (b == 0) {
        double invBN = 1.0 / (double)(BSZ * NPT);
        double total = g_acc[0] * invBN
                     + g_acc[1] * invBN
                     + ENT_WT * invBN * (g_acc[2] + g_acc[4] - g_acc[3])
                     + (double)cosv / (double)BSZ;
        out[0] = (float)total;
    }
}

// ------------------------- launch --------------------------------------------
extern "C" void kernel_launch(void* const* d_in, const int* in_sizes, int n_in,
                              void* d_out, int out_size) {
    const float* P1 = (const float*)d_in[0];
    const float* P2 = (const float*)d_in[1];
    const float* A1 = (const float*)d_in[2];
    const float* A2 = (const float*)d_in[3];
    const float* sc = (const float*)d_in[4];
    const float* rt = (const float*)d_in[5];
    const float* tr = (const float*)d_in[6];
    float* out = (float*)d_out;

    k_init<<<TOT/256, 256>>>(sc, rt, tr);
    k_pass1<<<dim3(BSZ, 128), 256>>>(A1, A2, P1, P2);
    k_pass2<<<512, 256>>>();
    k_colfinal<<<TOT/256, 256>>>();
    k_chamfer<<<128, 512>>>();
    k_final<<<1, 32>>>(out);
}

// round 7
// speedup vs baseline: 1.1737x; 1.0848x over previous
#include <cuda_runtime.h>
#include <cuda_fp16.h>
#include <cstdint>

#define BSZ 32
#define NPT 1024
#define NN (BSZ*NPT)      /* 32768 */
#define TOT (2*NN)        /* 65536 */

#define THRESH 0.1f
#define ENT_WT 1e-4

// ------------------------- scratch (device globals; no mallocs) -------------
__device__ uint32_t g_E[2u*BSZ*NPT*256];   // 64 MiB: exp(A) as e4m3, 4 per u32
__device__ float  g_Sr[TOT];
__device__ float  g_Tr[TOT];
__device__ float  g_invSr[TOT];
__device__ float4 g_U4[TOT];
__device__ float  g_Sc[TOT];
__device__ float  g_C[TOT];
__device__ float  g_ssq1[BSZ], g_ssq2[BSZ], g_dot[BSZ];
__device__ float  g_T12[BSZ*12], g_T21[BSZ*12];
__device__ float4 g_pin[TOT];   // mat0: p1in2, mat1: p2in1  (w = |p|^2)
__device__ float4 g_pto[TOT];   // mat0: p1to2, mat1: p2to1  (w = |p|^2)
__device__ double g_acc[6];     // 0 cham, 1 corr, 2 ent2, 3 entG, 4 colterm

// ------------------------- helpers ------------------------------------------
__device__ __forceinline__ float wsum(float v) {
#pragma unroll
    for (int o = 16; o; o >>= 1) v += __shfl_down_sync(0xffffffffu, v, o);
    return v;
}

__device__ __forceinline__ float block_sum(float v, float* sm) {
    int lane = threadIdx.x & 31, w = threadIdx.x >> 5;
    v = wsum(v);
    if (lane == 0) sm[w] = v;
    __syncthreads();
    int nw = (blockDim.x + 31) >> 5;
    v = (threadIdx.x < nw) ? sm[threadIdx.x] : 0.f;
    if (w == 0) v = wsum(v);
    return v;
}

// packed f32x2 helpers (FFMA2 — only reachable via PTX)
__device__ __forceinline__ unsigned long long pk2(float a, float b) {
    unsigned long long r;
    asm("mov.b64 %0, {%1,%2};" : "=l"(r) : "f"(a), "f"(b));
    return r;
}
__device__ __forceinline__ void upk2(unsigned long long v, float& a, float& b) {
    asm("mov.b64 {%0,%1}, %2;" : "=f"(a), "=f"(b) : "l"(v));
}
__device__ __forceinline__ unsigned long long mul2(unsigned long long a, unsigned long long b) {
    unsigned long long d;
    asm("mul.rn.f32x2 %0, %1, %2;" : "=l"(d) : "l"(a), "l"(b));
    return d;
}
__device__ __forceinline__ unsigned long long fma2(unsigned long long a, unsigned long long b,
                                                   unsigned long long c) {
    unsigned long long d;
    asm("fma.rn.f32x2 %0, %1, %2, %3;" : "=l"(d) : "l"(a), "l"(b), "l"(c));
    return d;
}

// fp8 e4m3 pack/unpack
__device__ __forceinline__ uint32_t pack_e4m3x4(float f0, float f1, float f2, float f3) {
    uint32_t r;
    asm("{\n\t.reg .b16 lo, hi;\n\t"
        "cvt.rn.satfinite.e4m3x2.f32 lo, %2, %1;\n\t"
        "cvt.rn.satfinite.e4m3x2.f32 hi, %4, %3;\n\t"
        "mov.b32 %0, {lo, hi};\n\t}"
        : "=r"(r) : "f"(f0), "f"(f1), "f"(f2), "f"(f3));
    return r;
}
__device__ __forceinline__ void unpack_e4m3x4(uint32_t v, uint32_t& h01, uint32_t& h23) {
    asm("{\n\t.reg .b16 lo, hi;\n\t"
        "mov.b32 {lo, hi}, %2;\n\t"
        "cvt.rn.f16x2.e4m3x2 %0, lo;\n\t"
        "cvt.rn.f16x2.e4m3x2 %1, hi;\n\t}"
        : "=r"(h01), "=r"(h23) : "r"(v));
}
__device__ __forceinline__ uint32_t hadd2u(uint32_t a, uint32_t b) {
    uint32_t d; asm("add.rn.f16x2 %0, %1, %2;" : "=r"(d) : "r"(a), "r"(b)); return d;
}
__device__ __forceinline__ uint32_t hfma2u(uint32_t a, uint32_t b, uint32_t c) {
    uint32_t d; asm("fma.rn.f16x2 %0, %1, %2, %3;" : "=r"(d) : "r"(a), "r"(b), "r"(c)); return d;
}
__device__ __forceinline__ uint32_t bcast_h2(float w) {
    uint32_t d;
    asm("{\n\t.reg .b16 h;\n\tcvt.rn.f16.f32 h, %1;\n\tmov.b32 %0, {h, h};\n\t}"
        : "=r"(d) : "f"(w));
    return d;
}
__device__ __forceinline__ void h2_to_f2(uint32_t v, float& a, float& b) {
    asm("{\n\t.reg .b16 lo, hi;\n\tmov.b32 {lo, hi}, %2;\n\t"
        "cvt.f32.f16 %0, lo;\n\tcvt.f32.f16 %1, hi;\n\t}"
        : "=f"(a), "=f"(b) : "r"(v));
}

// ------------------------- init ----------------------------------------------
__global__ void k_init() {
    int i = blockIdx.x * 256 + threadIdx.x;
    if (i < TOT) { g_Sc[i] = 0.f; g_C[i] = 0.f; }
    if (i < BSZ) { g_ssq1[i] = 0.f; g_ssq2[i] = 0.f; g_dot[i] = 0.f; }
}

// ------------------------- pose ------------------------------------------------
__global__ void k_pose(const float* __restrict__ scale,
                       const float* __restrict__ rot,
                       const float* __restrict__ trans) {
    int b = threadIdx.x;
    if (b >= BSZ) return;
    float s = scale[b];
    float m[9];
#pragma unroll
    for (int k = 0; k < 9; k++) m[k] = s * rot[b*9 + k];
    float t0 = trans[b*3+0], t1 = trans[b*3+1], t2 = trans[b*3+2];

    float* T = g_T12 + b*12;
    T[0]=m[0]; T[1]=m[1]; T[2]=m[2];  T[3]=t0;
    T[4]=m[3]; T[5]=m[4]; T[6]=m[5];  T[7]=t1;
    T[8]=m[6]; T[9]=m[7]; T[10]=m[8]; T[11]=t2;

    float c00=(m[4]*m[8]-m[5]*m[7]), c01=(m[2]*m[7]-m[1]*m[8]), c02=(m[1]*m[5]-m[2]*m[4]);
    float c10=(m[5]*m[6]-m[3]*m[8]), c11=(m[0]*m[8]-m[2]*m[6]), c12=(m[2]*m[3]-m[0]*m[5]);
    float c20=(m[3]*m[7]-m[4]*m[6]), c21=(m[1]*m[6]-m[0]*m[7]), c22=(m[0]*m[4]-m[1]*m[3]);
    float det = m[0]*c00 + m[1]*c10 + m[2]*c20;
    float id = 1.f/det;
    float i00=c00*id,i01=c01*id,i02=c02*id;
    float i10=c10*id,i11=c11*id,i12=c12*id;
    float i20=c20*id,i21=c21*id,i22=c22*id;
    float u0 = -(i00*t0 + i01*t1 + i02*t2);
    float u1 = -(i10*t0 + i11*t1 + i12*t2);
    float u2 = -(i20*t0 + i21*t1 + i22*t2);
    float* V = g_T21 + b*12;
    V[0]=i00; V[1]=i01; V[2]=i02;  V[3]=u0;
    V[4]=i10; V[5]=i11; V[6]=i12;  V[7]=u1;
    V[8]=i20; V[9]=i21; V[10]=i22; V[11]=u2;
}

// ------------------------- clear accumulators ---------------------------------
__global__ void k_clr() {
    if (threadIdx.x < 6) g_acc[threadIdx.x] = 0.0;
}

// ------------------------- pass 1 (round-3 structure + fp8 pack) --------------
// grid (32, 64), 256 threads (8 warps). block covers 16 rows of both matrices;
// warp w handles rows rb*16 + w*2 + {0,1}. Also writes exp(A) as e4m3 to g_E.
__global__ __launch_bounds__(256, 3)
void k_pass1(const float* __restrict__ A1, const float* __restrict__ A2,
             const float* __restrict__ P1, const float* __restrict__ P2) {
    __shared__ float p1x[NPT], p1y[NPT], p1z[NPT];
    __shared__ float p2x[NPT], p2y[NPT], p2z[NPT];
    __shared__ float rsm[32];

    int b = blockIdx.x;
    int rb = blockIdx.y;
    int tid = threadIdx.x;
    const float* P1g = P1 + (size_t)b*NPT*3;
    const float* P2g = P2 + (size_t)b*NPT*3;
    for (int i = tid; i < NPT; i += 256) {
        p1x[i]=P1g[i*3+0]; p1y[i]=P1g[i*3+1]; p1z[i]=P1g[i*3+2];
        p2x[i]=P2g[i*3+0]; p2y[i]=P2g[i*3+1]; p2z[i]=P2g[i*3+2];
    }
    __syncthreads();

    int warp = tid >> 5, lane = tid & 31;
    int r0 = rb*16 + warp*2;
    const float* A1b = A1 + ((size_t)b << 20) + ((size_t)r0 << 10);
    const float* A2b = A2 + ((size_t)b << 20) + ((size_t)r0 << 10);
    uint32_t* E1b = g_E + ((size_t)b << 18) + r0*256;
    uint32_t* E2b = g_E + ((size_t)(BSZ + b) << 18) + r0*256;

    float ss1 = 0.f, ss2 = 0.f, dp = 0.f;
    float s1[2]={0,0}, t1[2]={0,0}, u1x[2]={0,0}, u1y[2]={0,0}, u1z[2]={0,0};
    float s2[2]={0,0}, t2[2]={0,0}, u2x[2]={0,0}, u2y[2]={0,0}, u2z[2]={0,0};

#pragma unroll
    for (int c = 0; c < 8; c++) {
        int colb = c*128 + lane*4;
        float4 q2xv = *(const float4*)&p2x[colb];
        float4 q2yv = *(const float4*)&p2y[colb];
        float4 q2zv = *(const float4*)&p2z[colb];
        float4 q1xv = *(const float4*)&p1x[colb];
        float4 q1yv = *(const float4*)&p1y[colb];
        float4 q1zv = *(const float4*)&p1z[colb];
#pragma unroll
        for (int r = 0; r < 2; r++) {
            const float4 a1 = __ldcs((const float4*)&A1b[(size_t)r*NPT + colb]);
            const float4 a2 = __ldcs((const float4*)&A2b[(size_t)r*NPT + colb]);
            float e1_0, e1_1, e1_2, e1_3, e2_0, e2_1, e2_2, e2_3;
#define PROC(cmp, E1V, E2V) { \
    float a1v=a1.cmp, a2v=a2.cmp; \
    float e1=__expf(a1v), e2=__expf(a2v); \
    E1V=e1; E2V=e2; \
    s1[r]+=e1; t1[r]=fmaf(e1,a1v,t1[r]); \
    u1x[r]=fmaf(e1,q2xv.cmp,u1x[r]); u1y[r]=fmaf(e1,q2yv.cmp,u1y[r]); u1z[r]=fmaf(e1,q2zv.cmp,u1z[r]); \
    s2[r]+=e2; t2[r]=fmaf(e2,a2v,t2[r]); \
    u2x[r]=fmaf(e2,q1xv.cmp,u2x[r]); u2y[r]=fmaf(e2,q1yv.cmp,u2y[r]); u2z[r]=fmaf(e2,q1zv.cmp,u2z[r]); \
    ss1=fmaf(a1v,a1v,ss1); ss2=fmaf(a2v,a2v,ss2); dp=fmaf(a1v,a2v,dp); }
            PROC(x, e1_0, e2_0) PROC(y, e1_1, e2_1) PROC(z, e1_2, e2_2) PROC(w, e1_3, e2_3)
#undef PROC
            E1b[r*256 + c*32 + lane] = pack_e4m3x4(e1_0, e1_1, e1_2, e1_3);
            E2b[r*256 + c*32 + lane] = pack_e4m3x4(e2_0, e2_1, e2_2, e2_3);
        }
    }

#pragma unroll
    for (int r = 0; r < 2; r++) {
        int row = r0 + r;
        size_t i1 = (size_t)b*NPT + row;
        size_t i2 = (size_t)NN + i1;
        float vs = wsum(s1[r]);  float vt = wsum(t1[r]);
        float vx = wsum(u1x[r]); float vy = wsum(u1y[r]); float vz = wsum(u1z[r]);
        if (lane == 0) {
            g_Sr[i1]=vs; g_Tr[i1]=vt;
            g_U4[i1] = make_float4(vx, vy, vz, 0.f);
        }
        vs = wsum(s2[r]);  vt = wsum(t2[r]);
        vx = wsum(u2x[r]); vy = wsum(u2y[r]); vz = wsum(u2z[r]);
        if (lane == 0) {
            g_Sr[i2]=vs; g_Tr[i2]=vt;
            g_U4[i2] = make_float4(vx, vy, vz, 0.f);
        }
    }

    float v = block_sum(ss1, rsm);
    if (tid == 0) atomicAdd(&g_ssq1[b], v);
    __syncthreads();
    v = block_sum(ss2, rsm);
    if (tid == 0) atomicAdd(&g_ssq2[b], v);
    __syncthreads();
    v = block_sum(dp, rsm);
    if (tid == 0) atomicAdd(&g_dot[b], v);
}

// ------------------------- row finalize --------------------------------------
__global__ __launch_bounds__(256)
void k_rowfinal(const float* __restrict__ P1, const float* __restrict__ P2) {
    __shared__ float rsm[32];
    int idx = blockIdx.x * 256 + threadIdx.x;   // < 65536
    int mat = idx >> 15;
    int b   = (idx >> 10) & 31;
    int n   = idx & 1023;

    float sr  = g_Sr[idx];
    float isr = 1.f / sr;
    g_invSr[idx] = isr;
    float gq  = g_Tr[idx] * isr;                 // sum_m sa*A for this row
    float e2p = __logf(sr) - gq;

    float4 u = g_U4[idx];
    float px = u.x*isr, py = u.y*isr, pz = u.z*isr;
    g_pin[idx] = make_float4(px, py, pz, px*px+py*py+pz*pz);

    const float* pts = mat ? P2 : P1;
    const float* T   = (mat ? g_T21 : g_T12) + b*12;
    float x0 = pts[((size_t)b*NPT+n)*3+0];
    float x1 = pts[((size_t)b*NPT+n)*3+1];
    float x2 = pts[((size_t)b*NPT+n)*3+2];
    float y0 = T[0]*x0 + T[1]*x1 + T[2]*x2 + T[3];
    float y1 = T[4]*x0 + T[5]*x1 + T[6]*x2 + T[7];
    float y2 = T[8]*x0 + T[9]*x1 + T[10]*x2 + T[11];
    g_pto[idx] = make_float4(y0, y1, y2, y0*y0+y1*y1+y2*y2);

#define HUBER(d) ((d) > THRESH ? (d) - 0.5f*THRESH : (d)*(d)*(0.5f/THRESH))
    float d0 = fabsf(px-y0), d1 = fabsf(py-y1), d2 = fabsf(pz-y2);
    float corr = HUBER(d0) + HUBER(d1) + HUBER(d2);
#undef HUBER

    float v = block_sum(e2p, rsm);
    if (threadIdx.x == 0) atomicAdd(&g_acc[2], (double)v);
    __syncthreads();
    v = block_sum(gq, rsm);
    if (threadIdx.x == 0) atomicAdd(&g_acc[3], (double)v);
    __syncthreads();
    v = block_sum(corr, rsm);
    if (threadIdx.x == 0) atomicAdd(&g_acc[1], (double)v);
}

// ------------------------- pass 2: fp8 column pass ----------------------------
// grid 512: bx -> chunk(8, 128 rows) x b(32) x mat(2). 256 threads:
// sub = tid>>6 handles rows chunk*128+sub*32 .. +31; ct = tid&63 handles
// 16 columns (one uint4 of fp8 per row). Accumulate Sc/C in f16x2, flush f32.
__global__ __launch_bounds__(256)
void k_pass2() {
    __shared__ float isr[128];
    const int bx = blockIdx.x;
    const int chunk = bx & 7, b = (bx >> 3) & 31, mat = bx >> 8;
    const int tid = threadIdx.x;
    const int sub = tid >> 6, ct = tid & 63;

    if (tid < 128)
        isr[tid] = g_invSr[(size_t)(mat*BSZ + b)*NPT + chunk*128 + tid];
    __syncthreads();

    const int row0 = chunk*128 + sub*32;
    const uint4* Ep = (const uint4*)(g_E + ((size_t)(mat*BSZ + b) << 18) + row0*256) + ct;

    uint32_t sc[8], cc[8];
#pragma unroll
    for (int k = 0; k < 8; k++) { sc[k] = 0u; cc[k] = 0u; }

#pragma unroll 4
    for (int r = 0; r < 32; r++) {
        uint4 v = Ep[(size_t)r*64];
        uint32_t w2 = bcast_h2(isr[sub*32 + r]);
        uint32_t h0, h1;
        unpack_e4m3x4(v.x, h0, h1);
        sc[0]=hadd2u(sc[0],h0); cc[0]=hfma2u(h0,w2,cc[0]);
        sc[1]=hadd2u(sc[1],h1); cc[1]=hfma2u(h1,w2,cc[1]);
        unpack_e4m3x4(v.y, h0, h1);
        sc[2]=hadd2u(sc[2],h0); cc[2]=hfma2u(h0,w2,cc[2]);
        sc[3]=hadd2u(sc[3],h1); cc[3]=hfma2u(h1,w2,cc[3]);
        unpack_e4m3x4(v.z, h0, h1);
        sc[4]=hadd2u(sc[4],h0); cc[4]=hfma2u(h0,w2,cc[4]);
        sc[5]=hadd2u(sc[5],h1); cc[5]=hfma2u(h1,w2,cc[5]);
        unpack_e4m3x4(v.w, h0, h1);
        sc[6]=hadd2u(sc[6],h0); cc[6]=hfma2u(h0,w2,cc[6]);
        sc[7]=hadd2u(sc[7],h1); cc[7]=hfma2u(h1,w2,cc[7]);
    }

    const size_t o = (size_t)(mat*BSZ + b)*NPT + ct*16;
#pragma unroll
    for (int k = 0; k < 8; k++) {
        float a0, a1;
        h2_to_f2(sc[k], a0, a1);
        atomicAdd(&g_Sc[o + 2*k],     a0);
        atomicAdd(&g_Sc[o + 2*k + 1], a1);
        h2_to_f2(cc[k], a0, a1);
        atomicAdd(&g_C[o + 2*k],      a0);
        atomicAdd(&g_C[o + 2*k + 1],  a1);
    }
}

// ------------------------- column finalize -----------------------------------
__global__ __launch_bounds__(256)
void k_colfinal() {
    __shared__ float rsm[32];
    int i = blockIdx.x * 256 + threadIdx.x;   // < 65536
    float v = __logf(g_Sc[i]) * g_C[i];
    v = block_sum(v, rsm);
    if (threadIdx.x == 0) atomicAdd(&g_acc[4], (double)v);
}

// ------------------------- chamfer (packed f32x2) ----------------------------
// grid 128: bx -> b(32) x dir(2) x prob(2). 512 threads, 2 x-points each.
__global__ __launch_bounds__(512)
void k_chamfer() {
    __shared__ ulonglong2 sYA[NPT/2];   // (x-pair, y-pair)
    __shared__ ulonglong2 sYB[NPT/2];   // (z-pair, w-pair)
    __shared__ float rsm[32];
    int bx = blockIdx.x;
    int b = bx & 31; int dir = (bx >> 5) & 1; int prob = bx >> 6;
    size_t base = (size_t)(prob*BSZ + b) * NPT;
    const float4* X = dir ? (g_pin + base) : (g_pto + base);
    const float4* Y = dir ? (g_pto + base) : (g_pin + base);
    int tid = threadIdx.x;

    {
        float4 y0 = Y[2*tid], y1 = Y[2*tid+1];
        sYA[tid] = make_ulonglong2(pk2(y0.x, y1.x), pk2(y0.y, y1.y));
        sYB[tid] = make_ulonglong2(pk2(y0.z, y1.z), pk2(y0.w, y1.w));
    }
    __syncthreads();

    float4 xa = X[tid];
    float4 xb = X[tid + 512];
    unsigned long long ax = pk2(xa.x, xa.x), ay = pk2(xa.y, xa.y), az = pk2(xa.z, xa.z);
    unsigned long long bx2 = pk2(xb.x, xb.x), by = pk2(xb.y, xb.y), bz = pk2(xb.z, xb.z);
    const unsigned long long neg2 = pk2(-2.f, -2.f);

    float mna = 1e30f, mnb = 1e30f;
#pragma unroll 4
    for (int m = 0; m < NPT/2; m++) {
        ulonglong2 A = sYA[m];
        ulonglong2 B = sYB[m];
        unsigned long long d, v;
        float lo, hi;
        d = mul2(ax, A.x); d = fma2(ay, A.y, d); d = fma2(az, B.x, d);
        v = fma2(neg2, d, B.y);
        upk2(v, lo, hi);
        mna = fminf(mna, fminf(lo, hi));
        d = mul2(bx2, A.x); d = fma2(by, A.y, d); d = fma2(bz, B.x, d);
        v = fma2(neg2, d, B.y);
        upk2(v, lo, hi);
        mnb = fminf(mnb, fminf(lo, hi));
    }
    float dsum = fmaxf(xa.w + mna, 0.f) + fmaxf(xb.w + mnb, 0.f);
    float v = block_sum(dsum, rsm);
    if (tid == 0) atomicAdd(&g_acc[0], (double)v);
}

// ------------------------- final combine -------------------------------------
__global__ void k_final(float* __restrict__ out) {
    int b = threadIdx.x;   // 32 threads
    float n1 = sqrtf(g_ssq1[b]);
    float n2 = sqrtf(g_ssq2[b]);
    float cosv = 1.f - g_dot[b] / (fmaxf(n1, 1e-8f) * fmaxf(n2, 1e-8f));
    cosv = wsum(cosv);
    if (b == 0) {
        double invBN = 1.0 / (double)(BSZ * NPT);
        double total = g_acc[0] * invBN
                     + g_acc[1] * invBN
                     + ENT_WT * invBN * (g_acc[2] + g_acc[4] - g_acc[3])
                     + (double)cosv / (double)BSZ;
        out[0] = (float)total;
    }
}

// ------------------------- launch --------------------------------------------
extern "C" void kernel_launch(void* const* d_in, const int* in_sizes, int n_in,
                              void* d_out, int out_size) {
    const float* P1 = (const float*)d_in[0];
    const float* P2 = (const float*)d_in[1];
    const float* A1 = (const float*)d_in[2];
    const float* A2 = (const float*)d_in[3];
    const float* sc = (const float*)d_in[4];
    const float* rt = (const float*)d_in[5];
    const float* tr = (const float*)d_in[6];
    float* out = (float*)d_out;

    k_init<<<TOT/256, 256>>>();
    k_pose<<<1, 32>>>(sc, rt, tr);
    k_clr<<<1, 32>>>();
    k_pass1<<<dim3(BSZ, 64), 256>>>(A1, A2, P1, P2);   // 4th launch -> profiled
    k_rowfinal<<<TOT/256, 256>>>(P1, P2);
    k_pass2<<<512, 256>>>();
    k_colfinal<<<TOT/256, 256>>>();
    k_chamfer<<<128, 512>>>();
    k_final<<<1, 32>>>(out);
}

// round 8
// speedup vs baseline: 1.2156x; 1.0357x over previous
#include <cuda_runtime.h>
#include <cuda_fp16.h>
#include <cstdint>

#define BSZ 32
#define NPT 1024
#define NN (BSZ*NPT)      /* 32768 */
#define TOT (2*NN)        /* 65536 */

#define THRESH 0.1f
#define ENT_WT 1e-4

typedef unsigned long long ull;

// ------------------------- scratch (device globals; no mallocs) -------------
__device__ uint32_t g_E[2u*BSZ*NPT*256];   // 64 MiB: exp(A) as e4m3, 4 per u32
__device__ float  g_Sr[TOT];
__device__ float  g_Tr[TOT];
__device__ float  g_invSr[TOT];
__device__ float4 g_U4[TOT];
__device__ float  g_Sc[TOT];
__device__ float  g_C[TOT];
__device__ float  g_ssq1[BSZ], g_ssq2[BSZ], g_dot[BSZ];
__device__ float  g_T12[BSZ*12], g_T21[BSZ*12];
__device__ float4 g_pin[TOT];   // mat0: p1in2, mat1: p2in1  (w = |p|^2)
__device__ float4 g_pto[TOT];   // mat0: p1to2, mat1: p2to1  (w = |p|^2)
__device__ double g_acc[6];     // 0 cham, 1 corr, 2 ent2, 3 entG, 4 colterm

// ------------------------- helpers ------------------------------------------
__device__ __forceinline__ float wsum(float v) {
#pragma unroll
    for (int o = 16; o; o >>= 1) v += __shfl_down_sync(0xffffffffu, v, o);
    return v;
}

__device__ __forceinline__ float block_sum(float v, float* sm) {
    int lane = threadIdx.x & 31, w = threadIdx.x >> 5;
    v = wsum(v);
    if (lane == 0) sm[w] = v;
    __syncthreads();
    int nw = (blockDim.x + 31) >> 5;
    v = (threadIdx.x < nw) ? sm[threadIdx.x] : 0.f;
    if (w == 0) v = wsum(v);
    return v;
}

// packed f32x2 helpers
__device__ __forceinline__ ull pk2(float a, float b) {
    ull r;
    asm("mov.b64 %0, {%1,%2};" : "=l"(r) : "f"(a), "f"(b));
    return r;
}
__device__ __forceinline__ void upk2(ull v, float& a, float& b) {
    asm("mov.b64 {%0,%1}, %2;" : "=f"(a), "=f"(b) : "l"(v));
}
__device__ __forceinline__ ull mul2(ull a, ull b) {
    ull d;
    asm("mul.rn.f32x2 %0, %1, %2;" : "=l"(d) : "l"(a), "l"(b));
    return d;
}
__device__ __forceinline__ ull add2(ull a, ull b) {
    ull d;
    asm("add.rn.f32x2 %0, %1, %2;" : "=l"(d) : "l"(a), "l"(b));
    return d;
}
__device__ __forceinline__ ull fma2(ull a, ull b, ull c) {
    ull d;
    asm("fma.rn.f32x2 %0, %1, %2, %3;" : "=l"(d) : "l"(a), "l"(b), "l"(c));
    return d;
}
__device__ __forceinline__ float ex2f(float x) {
    float r; asm("ex2.approx.f32 %0, %1;" : "=f"(r) : "f"(x)); return r;
}
__device__ __forceinline__ float sum2(ull v) {
    float a, b; upk2(v, a, b); return a + b;
}

// fp8 e4m3 pack/unpack
__device__ __forceinline__ uint32_t pack_e4m3x4(float f0, float f1, float f2, float f3) {
    uint32_t r;
    asm("{\n\t.reg .b16 lo, hi;\n\t"
        "cvt.rn.satfinite.e4m3x2.f32 lo, %2, %1;\n\t"
        "cvt.rn.satfinite.e4m3x2.f32 hi, %4, %3;\n\t"
        "mov.b32 %0, {lo, hi};\n\t}"
        : "=r"(r) : "f"(f0), "f"(f1), "f"(f2), "f"(f3));
    return r;
}
__device__ __forceinline__ void unpack_e4m3x4(uint32_t v, uint32_t& h01, uint32_t& h23) {
    asm("{\n\t.reg .b16 lo, hi;\n\t"
        "mov.b32 {lo, hi}, %2;\n\t"
        "cvt.rn.f16x2.e4m3x2 %0, lo;\n\t"
        "cvt.rn.f16x2.e4m3x2 %1, hi;\n\t}"
        : "=r"(h01), "=r"(h23) : "r"(v));
}
__device__ __forceinline__ uint32_t hadd2u(uint32_t a, uint32_t b) {
    uint32_t d; asm("add.rn.f16x2 %0, %1, %2;" : "=r"(d) : "r"(a), "r"(b)); return d;
}
__device__ __forceinline__ uint32_t hfma2u(uint32_t a, uint32_t b, uint32_t c) {
    uint32_t d; asm("fma.rn.f16x2 %0, %1, %2, %3;" : "=r"(d) : "r"(a), "r"(b), "r"(c)); return d;
}
__device__ __forceinline__ uint32_t bcast_h2(float w) {
    uint32_t d;
    asm("{\n\t.reg .b16 h;\n\tcvt.rn.f16.f32 h, %1;\n\tmov.b32 %0, {h, h};\n\t}"
        : "=r"(d) : "f"(w));
    return d;
}
__device__ __forceinline__ void h2_to_f2(uint32_t v, float& a, float& b) {
    asm("{\n\t.reg .b16 lo, hi;\n\tmov.b32 {lo, hi}, %2;\n\t"
        "cvt.f32.f16 %0, lo;\n\tcvt.f32.f16 %1, hi;\n\t}"
        : "=f"(a), "=f"(b) : "r"(v));
}

// ------------------------- init ----------------------------------------------
__global__ void k_init() {
    int i = blockIdx.x * 256 + threadIdx.x;
    if (i < TOT) { g_Sc[i] = 0.f; g_C[i] = 0.f; }
    if (i < BSZ) { g_ssq1[i] = 0.f; g_ssq2[i] = 0.f; g_dot[i] = 0.f; }
}

// ------------------------- pose ------------------------------------------------
__global__ void k_pose(const float* __restrict__ scale,
                       const float* __restrict__ rot,
                       const float* __restrict__ trans) {
    int b = threadIdx.x;
    if (b >= BSZ) return;
    float s = scale[b];
    float m[9];
#pragma unroll
    for (int k = 0; k < 9; k++) m[k] = s * rot[b*9 + k];
    float t0 = trans[b*3+0], t1 = trans[b*3+1], t2 = trans[b*3+2];

    float* T = g_T12 + b*12;
    T[0]=m[0]; T[1]=m[1]; T[2]=m[2];  T[3]=t0;
    T[4]=m[3]; T[5]=m[4]; T[6]=m[5];  T[7]=t1;
    T[8]=m[6]; T[9]=m[7]; T[10]=m[8]; T[11]=t2;

    float c00=(m[4]*m[8]-m[5]*m[7]), c01=(m[2]*m[7]-m[1]*m[8]), c02=(m[1]*m[5]-m[2]*m[4]);
    float c10=(m[5]*m[6]-m[3]*m[8]), c11=(m[0]*m[8]-m[2]*m[6]), c12=(m[2]*m[3]-m[0]*m[5]);
    float c20=(m[3]*m[7]-m[4]*m[6]), c21=(m[1]*m[6]-m[0]*m[7]), c22=(m[0]*m[4]-m[1]*m[3]);
    float det = m[0]*c00 + m[1]*c10 + m[2]*c20;
    float id = 1.f/det;
    float i00=c00*id,i01=c01*id,i02=c02*id;
    float i10=c10*id,i11=c11*id,i12=c12*id;
    float i20=c20*id,i21=c21*id,i22=c22*id;
    float u0 = -(i00*t0 + i01*t1 + i02*t2);
    float u1 = -(i10*t0 + i11*t1 + i12*t2);
    float u2 = -(i20*t0 + i21*t1 + i22*t2);
    float* V = g_T21 + b*12;
    V[0]=i00; V[1]=i01; V[2]=i02;  V[3]=u0;
    V[4]=i10; V[5]=i11; V[6]=i12;  V[7]=u1;
    V[8]=i20; V[9]=i21; V[10]=i22; V[11]=u2;
}

// ------------------------- clear accumulators ---------------------------------
__global__ void k_clr() {
    if (threadIdx.x < 6) g_acc[threadIdx.x] = 0.0;
}

// ------------------------- pass 1 (packed f32x2, 1 row/warp) ------------------
// grid (32, 128), 256 threads = 8 warps; warp w owns row rb*8+w of both
// matrices. Per c-iter each thread handles one float4 of each matrix.
// Also writes exp(A) as e4m3 to g_E.
__global__ __launch_bounds__(256, 4)
void k_pass1(const float* __restrict__ A1, const float* __restrict__ A2,
             const float* __restrict__ P1, const float* __restrict__ P2) {
    __shared__ ull s1x[NPT/2], s1y[NPT/2], s1z[NPT/2];
    __shared__ ull s2x[NPT/2], s2y[NPT/2], s2z[NPT/2];
    __shared__ float rsm[32];

    const int b  = blockIdx.x;
    const int rb = blockIdx.y;
    const int tid = threadIdx.x;
    const int warp = tid >> 5, lane = tid & 31;

    const float* P1g = P1 + (size_t)b*NPT*3;
    const float* P2g = P2 + (size_t)b*NPT*3;
    for (int i = tid; i < NPT/2; i += 256) {
        const float* b1 = P1g + 6*i;
        s1x[i] = pk2(b1[0], b1[3]);
        s1y[i] = pk2(b1[1], b1[4]);
        s1z[i] = pk2(b1[2], b1[5]);
        const float* b2 = P2g + 6*i;
        s2x[i] = pk2(b2[0], b2[3]);
        s2y[i] = pk2(b2[1], b2[4]);
        s2z[i] = pk2(b2[2], b2[5]);
    }
    __syncthreads();

    const int row = rb*8 + warp;
    const float* A1r = A1 + ((size_t)b << 20) + ((size_t)row << 10);
    const float* A2r = A2 + ((size_t)b << 20) + ((size_t)row << 10);
    uint32_t* E1r = g_E + ((size_t)b << 18) + row*256;
    uint32_t* E2r = g_E + ((size_t)(BSZ + b) << 18) + row*256;

    const ull L2E = pk2(1.4426950408889634f, 1.4426950408889634f);

    ull sP1=0, tP1=0, uxP1=0, uyP1=0, uzP1=0;
    ull sP2=0, tP2=0, uxP2=0, uyP2=0, uzP2=0;
    ull ssP1=0, ssP2=0, dpP=0;

#pragma unroll
    for (int c = 0; c < 8; c++) {
        const int col = c*128 + lane*4;
        const float4 a1 = __ldcs((const float4*)&A1r[col]);
        const float4 a2 = __ldcs((const float4*)&A2r[col]);
        const ulonglong2 q2x = *(const ulonglong2*)&s2x[col >> 1];
        const ulonglong2 q2y = *(const ulonglong2*)&s2y[col >> 1];
        const ulonglong2 q2z = *(const ulonglong2*)&s2z[col >> 1];
        const ulonglong2 q1x = *(const ulonglong2*)&s1x[col >> 1];
        const ulonglong2 q1y = *(const ulonglong2*)&s1y[col >> 1];
        const ulonglong2 q1z = *(const ulonglong2*)&s1z[col >> 1];

        // ---- matrix 1
        {
            ull a01 = pk2(a1.x, a1.y), a23 = pk2(a1.z, a1.w);
            ull x01 = mul2(a01, L2E),  x23 = mul2(a23, L2E);
            float f0, f1, f2, f3;
            upk2(x01, f0, f1); upk2(x23, f2, f3);
            float e0 = ex2f(f0), e1 = ex2f(f1), e2 = ex2f(f2), e3 = ex2f(f3);
            ull e01 = pk2(e0, e1), e23 = pk2(e2, e3);
            sP1 = add2(sP1, e01);      sP1 = add2(sP1, e23);
            tP1 = fma2(e01, a01, tP1); tP1 = fma2(e23, a23, tP1);
            uxP1 = fma2(e01, q2x.x, uxP1); uxP1 = fma2(e23, q2x.y, uxP1);
            uyP1 = fma2(e01, q2y.x, uyP1); uyP1 = fma2(e23, q2y.y, uyP1);
            uzP1 = fma2(e01, q2z.x, uzP1); uzP1 = fma2(e23, q2z.y, uzP1);
            ssP1 = fma2(a01, a01, ssP1);   ssP1 = fma2(a23, a23, ssP1);
            E1r[col >> 2] = pack_e4m3x4(e0, e1, e2, e3);
            // dp uses a2 pairs below
            ull b01 = pk2(a2.x, a2.y), b23 = pk2(a2.z, a2.w);
            dpP = fma2(a01, b01, dpP); dpP = fma2(a23, b23, dpP);
            ssP2 = fma2(b01, b01, ssP2);   ssP2 = fma2(b23, b23, ssP2);
            // ---- matrix 2
            ull y01 = mul2(b01, L2E), y23 = mul2(b23, L2E);
            float g0, g1, g2, g3;
            upk2(y01, g0, g1); upk2(y23, g2, g3);
            float h0 = ex2f(g0), h1 = ex2f(g1), h2 = ex2f(g2), h3 = ex2f(g3);
            ull h01 = pk2(h0, h1), h23 = pk2(h2, h3);
            sP2 = add2(sP2, h01);      sP2 = add2(sP2, h23);
            tP2 = fma2(h01, b01, tP2); tP2 = fma2(h23, b23, tP2);
            uxP2 = fma2(h01, q1x.x, uxP2); uxP2 = fma2(h23, q1x.y, uxP2);
            uyP2 = fma2(h01, q1y.x, uyP2); uyP2 = fma2(h23, q1y.y, uyP2);
            uzP2 = fma2(h01, q1z.x, uzP2); uzP2 = fma2(h23, q1z.y, uzP2);
            E2r[col >> 2] = pack_e4m3x4(h0, h1, h2, h3);
        }
    }

    // ---- per-row reductions (warp-local; 1 row per warp)
    float s1 = wsum(sum2(sP1)),  t1 = wsum(sum2(tP1));
    float ux1 = wsum(sum2(uxP1)), uy1 = wsum(sum2(uyP1)), uz1 = wsum(sum2(uzP1));
    float s2v = wsum(sum2(sP2)),  t2v = wsum(sum2(tP2));
    float ux2 = wsum(sum2(uxP2)), uy2 = wsum(sum2(uyP2)), uz2 = wsum(sum2(uzP2));
    if (lane == 0) {
        size_t i1 = (size_t)b*NPT + row;
        size_t i2 = (size_t)NN + i1;
        g_Sr[i1] = s1; g_Tr[i1] = t1;
        g_U4[i1] = make_float4(ux1, uy1, uz1, 0.f);
        g_Sr[i2] = s2v; g_Tr[i2] = t2v;
        g_U4[i2] = make_float4(ux2, uy2, uz2, 0.f);
    }

    // ---- block sums for ssq / dot
    float v = block_sum(sum2(ssP1), rsm);
    if (tid == 0) atomicAdd(&g_ssq1[b], v);
    __syncthreads();
    v = block_sum(sum2(ssP2), rsm);
    if (tid == 0) atomicAdd(&g_ssq2[b], v);
    __syncthreads();
    v = block_sum(sum2(dpP), rsm);
    if (tid == 0) atomicAdd(&g_dot[b], v);
}

// ------------------------- row finalize --------------------------------------
__global__ __launch_bounds__(256)
void k_rowfinal(const float* __restrict__ P1, const float* __restrict__ P2) {
    __shared__ float rsm[32];
    int idx = blockIdx.x * 256 + threadIdx.x;   // < 65536
    int mat = idx >> 15;
    int b   = (idx >> 10) & 31;
    int n   = idx & 1023;

    float sr  = g_Sr[idx];
    float isr = 1.f / sr;
    g_invSr[idx] = isr;
    float gq  = g_Tr[idx] * isr;                 // sum_m sa*A for this row
    float e2p = __logf(sr) - gq;

    float4 u = g_U4[idx];
    float px = u.x*isr, py = u.y*isr, pz = u.z*isr;
    g_pin[idx] = make_float4(px, py, pz, px*px+py*py+pz*pz);

    const float* pts = mat ? P2 : P1;
    const float* T   = (mat ? g_T21 : g_T12) + b*12;
    float x0 = pts[((size_t)b*NPT+n)*3+0];
    float x1 = pts[((size_t)b*NPT+n)*3+1];
    float x2 = pts[((size_t)b*NPT+n)*3+2];
    float y0 = T[0]*x0 + T[1]*x1 + T[2]*x2 + T[3];
    float y1 = T[4]*x0 + T[5]*x1 + T[6]*x2 + T[7];
    float y2 = T[8]*x0 + T[9]*x1 + T[10]*x2 + T[11];
    g_pto[idx] = make_float4(y0, y1, y2, y0*y0+y1*y1+y2*y2);

#define HUBER(d) ((d) > THRESH ? (d) - 0.5f*THRESH : (d)*(d)*(0.5f/THRESH))
    float d0 = fabsf(px-y0), d1 = fabsf(py-y1), d2 = fabsf(pz-y2);
    float corr = HUBER(d0) + HUBER(d1) + HUBER(d2);
#undef HUBER

    float v = block_sum(e2p, rsm);
    if (threadIdx.x == 0) atomicAdd(&g_acc[2], (double)v);
    __syncthreads();
    v = block_sum(gq, rsm);
    if (threadIdx.x == 0) atomicAdd(&g_acc[3], (double)v);
    __syncthreads();
    v = block_sum(corr, rsm);
    if (threadIdx.x == 0) atomicAdd(&g_acc[1], (double)v);
}

// ------------------------- pass 2: fp8 column pass ----------------------------
// grid 512: bx -> chunk(8, 128 rows) x b(32) x mat(2). 256 threads:
// sub = tid>>6 handles rows chunk*128+sub*32 .. +31; ct = tid&63 handles
// 16 columns (one uint4 of fp8 per row). Accumulate Sc/C in f16x2, flush f32.
__global__ __launch_bounds__(256)
void k_pass2() {
    __shared__ float isr[128];
    const int bx = blockIdx.x;
    const int chunk = bx & 7, b = (bx >> 3) & 31, mat = bx >> 8;
    const int tid = threadIdx.x;
    const int sub = tid >> 6, ct = tid & 63;

    if (tid < 128)
        isr[tid] = g_invSr[(size_t)(mat*BSZ + b)*NPT + chunk*128 + tid];
    __syncthreads();

    const int row0 = chunk*128 + sub*32;
    const uint4* Ep = (const uint4*)(g_E + ((size_t)(mat*BSZ + b) << 18) + row0*256) + ct;

    uint32_t sc[8], cc[8];
#pragma unroll
    for (int k = 0; k < 8; k++) { sc[k] = 0u; cc[k] = 0u; }

#pragma unroll 4
    for (int r = 0; r < 32; r++) {
        uint4 v = Ep[(size_t)r*64];
        uint32_t w2 = bcast_h2(isr[sub*32 + r]);
        uint32_t h0, h1;
        unpack_e4m3x4(v.x, h0, h1);
        sc[0]=hadd2u(sc[0],h0); cc[0]=hfma2u(h0,w2,cc[0]);
        sc[1]=hadd2u(sc[1],h1); cc[1]=hfma2u(h1,w2,cc[1]);
        unpack_e4m3x4(v.y, h0, h1);
        sc[2]=hadd2u(sc[2],h0); cc[2]=hfma2u(h0,w2,cc[2]);
        sc[3]=hadd2u(sc[3],h1); cc[3]=hfma2u(h1,w2,cc[3]);
        unpack_e4m3x4(v.z, h0, h1);
        sc[4]=hadd2u(sc[4],h0); cc[4]=hfma2u(h0,w2,cc[4]);
        sc[5]=hadd2u(sc[5],h1); cc[5]=hfma2u(h1,w2,cc[5]);
        unpack_e4m3x4(v.w, h0, h1);
        sc[6]=hadd2u(sc[6],h0); cc[6]=hfma2u(h0,w2,cc[6]);
        sc[7]=hadd2u(sc[7],h1); cc[7]=hfma2u(h1,w2,cc[7]);
    }

    const size_t o = (size_t)(mat*BSZ + b)*NPT + ct*16;
#pragma unroll
    for (int k = 0; k < 8; k++) {
        float a0, a1;
        h2_to_f2(sc[k], a0, a1);
        atomicAdd(&g_Sc[o + 2*k],     a0);
        atomicAdd(&g_Sc[o + 2*k + 1], a1);
        h2_to_f2(cc[k], a0, a1);
        atomicAdd(&g_C[o + 2*k],      a0);
        atomicAdd(&g_C[o + 2*k + 1],  a1);
    }
}

// ------------------------- column finalize -----------------------------------
__global__ __launch_bounds__(256)
void k_colfinal() {
    __shared__ float rsm[32];
    int i = blockIdx.x * 256 + threadIdx.x;   // < 65536
    float v = __logf(g_Sc[i]) * g_C[i];
    v = block_sum(v, rsm);
    if (threadIdx.x == 0) atomicAdd(&g_acc[4], (double)v);
}

// ------------------------- chamfer (packed f32x2) ----------------------------
// grid 128: bx -> b(32) x dir(2) x prob(2). 512 threads, 2 x-points each.
__global__ __launch_bounds__(512)
void k_chamfer() {
    __shared__ ulonglong2 sYA[NPT/2];   // (x-pair, y-pair)
    __shared__ ulonglong2 sYB[NPT/2];   // (z-pair, w-pair)
    __shared__ float rsm[32];
    int bx = blockIdx.x;
    int b = bx & 31; int dir = (bx >> 5) & 1; int prob = bx >> 6;
    size_t base = (size_t)(prob*BSZ + b) * NPT;
    const float4* X = dir ? (g_pin + base) : (g_pto + base);
    const float4* Y = dir ? (g_pto + base) : (g_pin + base);
    int tid = threadIdx.x;

    {
        float4 y0 = Y[2*tid], y1 = Y[2*tid+1];
        sYA[tid] = make_ulonglong2(pk2(y0.x, y1.x), pk2(y0.y, y1.y));
        sYB[tid] = make_ulonglong2(pk2(y0.z, y1.z), pk2(y0.w, y1.w));
    }
    __syncthreads();

    float4 xa = X[tid];
    float4 xb = X[tid + 512];
    ull ax = pk2(xa.x, xa.x), ay = pk2(xa.y, xa.y), az = pk2(xa.z, xa.z);
    ull bx2 = pk2(xb.x, xb.x), by = pk2(xb.y, xb.y), bz = pk2(xb.z, xb.z);
    const ull neg2 = pk2(-2.f, -2.f);

    float mna = 1e30f, mnb = 1e30f;
#pragma unroll 4
    for (int m = 0; m < NPT/2; m++) {
        ulonglong2 A = sYA[m];
        ulonglong2 B = sYB[m];
        ull d, v;
        float lo, hi;
        d = mul2(ax, A.x); d = fma2(ay, A.y, d); d = fma2(az, B.x, d);
        v = fma2(neg2, d, B.y);
        upk2(v, lo, hi);
        mna = fminf(mna, fminf(lo, hi));
        d = mul2(bx2, A.x); d = fma2(by, A.y, d); d = fma2(bz, B.x, d);
        v = fma2(neg2, d, B.y);
        upk2(v, lo, hi);
        mnb = fminf(mnb, fminf(lo, hi));
    }
    float dsum = fmaxf(xa.w + mna, 0.f) + fmaxf(xb.w + mnb, 0.f);
    float v = block_sum(dsum, rsm);
    if (tid == 0) atomicAdd(&g_acc[0], (double)v);
}

// ------------------------- final combine -------------------------------------
__global__ void k_final(float* __restrict__ out) {
    int b = threadIdx.x;   // 32 threads
    float n1 = sqrtf(g_ssq1[b]);
    float n2 = sqrtf(g_ssq2[b]);
    float cosv = 1.f - g_dot[b] / (fmaxf(n1, 1e-8f) * fmaxf(n2, 1e-8f));
    cosv = wsum(cosv);
    if (b == 0) {
        double invBN = 1.0 / (double)(BSZ * NPT);
        double total = g_acc[0] * invBN
                     + g_acc[1] * invBN
                     + ENT_WT * invBN * (g_acc[2] + g_acc[4] - g_acc[3])
                     + (double)cosv / (double)BSZ;
        out[0] = (float)total;
    }
}

// ------------------------- launch --------------------------------------------
extern "C" void kernel_launch(void* const* d_in, const int* in_sizes, int n_in,
                              void* d_out, int out_size) {
    const float* P1 = (const float*)d_in[0];
    const float* P2 = (const float*)d_in[1];
    const float* A1 = (const float*)d_in[2];
    const float* A2 = (const float*)d_in[3];
    const float* sc = (const float*)d_in[4];
    const float* rt = (const float*)d_in[5];
    const float* tr = (const float*)d_in[6];
    float* out = (float*)d_out;

    k_init<<<TOT/256, 256>>>();
    k_pose<<<1, 32>>>(sc, rt, tr);
    k_clr<<<1, 32>>>();
    k_pass1<<<dim3(BSZ, 128), 256>>>(A1, A2, P1, P2);   // 4th launch -> profiled
    k_rowfinal<<<TOT/256, 256>>>(P1, P2);
    k_pass2<<<512, 256>>>();
    k_colfinal<<<TOT/256, 256>>>();
    k_chamfer<<<128, 512>>>();
    k_final<<<1, 32>>>(out);
}